// round 14
// baseline (speedup 1.0000x reference)
#include <cuda_runtime.h>
#include <cuda_fp16.h>
#include <cstdint>

// Problem constants
#define NHEADS 16
#define DHEAD  128
#define SEQ    2048
#define BATCH  4
#define DIM    2048
#define BHTOT  (BATCH * NHEADS)   // 64

// NOTE (R9 lesson): harness compiles with -arch=sm_100 (no 'a' suffix) —
// tcgen05/TMEM are NOT available. Legacy mma.sync + ldmatrix only.

// Scratch (device globals: allocation-free per harness rules) — fp16 operands
__device__ __half g_Q[(size_t)BHTOT * SEQ * DHEAD];     // [bh][n][d]
__device__ __half g_K[(size_t)BHTOT * SEQ * DHEAD];     // [bh][n][d]
__device__ __half g_V[(size_t)BHTOT * DHEAD * SEQ];     // [bh][d][n] transposed
__device__ __half g_O[(size_t)BATCH * SEQ * DIM];       // [b][n][h*d]
__device__ __half g_X[(size_t)BATCH * SEQ * DIM];       // fp16 copy of x
__device__ __half g_Wqkv[(size_t)3 * DIM * DIM];        // fp16 copy of w_qkv
__device__ __half g_Wout[(size_t)DIM * DIM];            // fp16 copy of w_out

// ---------------------------------------------------------------------------
// Helpers
// ---------------------------------------------------------------------------
__device__ __forceinline__ void mma_f16(float* c, const uint32_t* a, uint32_t b0, uint32_t b1) {
    asm volatile(
        "mma.sync.aligned.m16n8k16.row.col.f32.f16.f16.f32 "
        "{%0,%1,%2,%3}, {%4,%5,%6,%7}, {%8,%9}, {%0,%1,%2,%3};\n"
        : "+f"(c[0]), "+f"(c[1]), "+f"(c[2]), "+f"(c[3])
        : "r"(a[0]), "r"(a[1]), "r"(a[2]), "r"(a[3]), "r"(b0), "r"(b1));
}

// ldmatrix x4: four 8x8 b16 matrices; lane l of matrix m gets (l/4, 2(l%4)).
__device__ __forceinline__ void ldsm_x4(uint32_t* r, uint32_t addr) {
    asm volatile("ldmatrix.sync.aligned.m8n8.x4.shared.b16 {%0,%1,%2,%3}, [%4];"
        : "=r"(r[0]), "=r"(r[1]), "=r"(r[2]), "=r"(r[3]) : "r"(addr));
}

__device__ __forceinline__ void cp16s(uint32_t sa, const void* g) {
    asm volatile("cp.async.cg.shared.global [%0], [%1], 16;\n" :: "r"(sa), "l"(g));
}
#define CP_COMMIT() asm volatile("cp.async.commit_group;\n" ::: "memory")
#define CP_WAIT1()  asm volatile("cp.async.wait_group 1;\n" ::: "memory")
#define CP_WAIT0()  asm volatile("cp.async.wait_group 0;\n" ::: "memory")

__device__ __forceinline__ uint32_t h2u(__half2 h) { return *(uint32_t*)&h; }

// ---------------------------------------------------------------------------
// Prepass: fp32 -> fp16 (RN), float4 -> 4 halves (uint2).
// ---------------------------------------------------------------------------
__global__ __launch_bounds__(256)
void round_half(const float4* __restrict__ src, uint2* __restrict__ dst, int n4)
{
    int i = blockIdx.x * blockDim.x + threadIdx.x;
    if (i < n4) {
        float4 v = src[i];
        __half2 a = __floats2half2_rn(v.x, v.y);
        __half2 b = __floats2half2_rn(v.z, v.w);
        dst[i] = make_uint2(h2u(a), h2u(b));
    }
}

// ---------------------------------------------------------------------------
// NT GEMM (fp16): C[M,N] = A[M,K] * B[N,K]^T, K contiguous halves.
// CTA tile 128x64 (M x N), warp tile 16x64: 8 warps stacked along M.
// acc = 32 regs/thread -> __launch_bounds__(256,3) = 3 CTAs/SM, 24 warps.
// BK=32 halves, 3-stage cp.async ring. Stage = A(128 rows)+B(64 rows),
// BKP=20 half2 words/row (80 B; ldmatrix conflict-free, cp.async-aligned).
// MODE 0: A=g_X, B=g_Wqkv -> scatter g_Q / g_K / g_V(transposed), fp16
// MODE 3: A=g_O, B=g_Wout, +bias -> d_out fp32 (written from fp32 acc)
// ---------------------------------------------------------------------------
#define BKP 20                                   // half2 words per smem row
#define STAGE_W (192 * BKP)                      // A(128)+B(64) rows, words
#define GEMM_SMEM_BYTES (3 * STAGE_W * 4)        // 46,080

template <int MODE>
__global__ __launch_bounds__(256, 3)
void gemm_nt(const float* __restrict__ bias, float* __restrict__ Cout, int K)
{
    extern __shared__ uint32_t sg[];

    const int tid  = threadIdx.x;
    const int lane = tid & 31;
    const int wid  = tid >> 5;      // 0..7 = M-tile index
    const int g    = lane >> 2;
    const int tig  = lane & 3;
    const int bm   = blockIdx.y;
    const int bn   = blockIdx.x;

    // ldmatrix per-lane offsets
    const int lr8   = lane & 7;
    const int arow  = lr8 + ((lane & 8)  ? 8 : 0);   // A-type: rows by bit3
    const int acolw = (lane & 16) ? 4 : 0;           //         k by bit4
    const int brow  = lr8 + ((lane & 16) ? 8 : 0);   // B-type: rows by bit4
    const int bcolw = (lane & 8)  ? 4 : 0;           //         k by bit3

    const __half* A = (MODE == 3) ? g_O : g_X;
    const __half* B = (MODE == 3) ? g_Wout : g_Wqkv;
    const __half* Arow_g = A + (size_t)(bm * 128) * K;
    const __half* Brow_g = B + (size_t)(bn * 64) * K;

    uint32_t sbase;
    asm("{ .reg .u64 t; cvta.to.shared.u64 t, %1; cvt.u32.u64 %0, t; }"
        : "=r"(sbase) : "l"(sg));

    float acc[8][4];
    #pragma unroll
    for (int nt = 0; nt < 8; nt++)
        #pragma unroll
        for (int i = 0; i < 4; i++) acc[nt][i] = 0.f;

    const int KT = K / 32;

    // per stage: A = 512 chunks (2/thread), B = 256 chunks (1/thread)
    auto load_stage = [&](int s, int kt) {
        uint32_t st = sbase + (uint32_t)s * STAGE_W * 4u;
        #pragma unroll
        for (int i = 0; i < 2; i++) {
            int idx = i * 256 + tid;
            int row = idx >> 2, c4 = idx & 3;
            cp16s(st + (uint32_t)(row * BKP + c4 * 4) * 4u,
                  Arow_g + (size_t)row * K + kt * 32 + c4 * 8);
        }
        {
            int row = tid >> 2, c4 = tid & 3;
            cp16s(st + (uint32_t)(128 * BKP + row * BKP + c4 * 4) * 4u,
                  Brow_g + (size_t)row * K + kt * 32 + c4 * 8);
        }
        CP_COMMIT();
    };

    load_stage(0, 0);
    load_stage(1, 1);

    int rbuf = 0;
    for (int kt = 0; kt < KT; kt++) {
        if (kt + 1 < KT) { CP_WAIT1(); } else { CP_WAIT0(); }
        __syncthreads();

        if (kt + 2 < KT) {
            int wbuf = rbuf + 2; if (wbuf >= 3) wbuf -= 3;
            load_stage(wbuf, kt + 2);
        }

        const uint32_t aA = sbase + (uint32_t)rbuf * STAGE_W * 4u;
        const uint32_t aB = aA + 128u * BKP * 4u;
        #pragma unroll
        for (int ks = 0; ks < 2; ks++) {
            uint32_t afr[4];
            int row = wid * 16 + arow;
            ldsm_x4(afr, aA + (uint32_t)(row * BKP + ks * 8 + acolw) * 4u);
            #pragma unroll
            for (int ntp = 0; ntp < 4; ntp++) {
                int nrow = ntp * 16 + brow;
                uint32_t bfr[4];
                ldsm_x4(bfr, aB + (uint32_t)(nrow * BKP + ks * 8 + bcolw) * 4u);
                mma_f16(acc[2 * ntp],     afr, bfr[0], bfr[1]);
                mma_f16(acc[2 * ntp + 1], afr, bfr[2], bfr[3]);
            }
        }

        if (++rbuf == 3) rbuf = 0;
    }

    #pragma unroll
    for (int nt = 0; nt < 8; nt++) {
        int row0 = bm * 128 + wid * 16 + g;
        int col  = bn * 64 + nt * 8 + 2 * tig;
        #pragma unroll
        for (int rr = 0; rr < 2; rr++) {
            int row = row0 + rr * 8;
            float x0 = acc[nt][rr * 2 + 0];
            float x1 = acc[nt][rr * 2 + 1];
            if (MODE == 0) {
                int b = row >> 11, pos = row & 2047;
                int which = col >> 11, rem = col & 2047;
                int h = rem >> 7, d = rem & 127;
                int bhh = (b << 4) + h;
                if (which == 2) {
                    g_V[((size_t)bhh * DHEAD + d)     * SEQ + pos] = __float2half_rn(x0);
                    g_V[((size_t)bhh * DHEAD + d + 1) * SEQ + pos] = __float2half_rn(x1);
                } else if (which == 0) {
                    *(__half2*)(g_Q + ((size_t)bhh * SEQ + pos) * DHEAD + d) =
                        __floats2half2_rn(x0, x1);
                } else {
                    *(__half2*)(g_K + ((size_t)bhh * SEQ + pos) * DHEAD + d) =
                        __floats2half2_rn(x0, x1);
                }
            } else {
                *(float2*)(Cout + (size_t)row * DIM + col) =
                    make_float2(x0 + bias[col], x1 + bias[col + 1]);
            }
        }
    }
}

// ---------------------------------------------------------------------------
// RoPE: in-place on fp16 g_Q, g_K (compute fp32, store fp16).
// ---------------------------------------------------------------------------
__global__ __launch_bounds__(256)
void rope_kernel()
{
    int t = blockIdx.x * blockDim.x + threadIdx.x;   // 64*2048*64 threads
    int i   = t & 63;
    int pos = (t >> 6) & 2047;
    int bh  = t >> 17;
    float p = (float)(2 * i) * (1.0f / 128.0f);
    float inv_freq = powf(10000.0f, -p);
    float fr = (float)pos * inv_freq;
    float s, c;
    sincosf(fr, &s, &c);
    size_t base = ((size_t)bh * SEQ + pos) * DHEAD;

    float q1 = __half2float(g_Q[base + i]), q2 = __half2float(g_Q[base + i + 64]);
    g_Q[base + i]      = __float2half_rn(q1 * c - q2 * s);
    g_Q[base + i + 64] = __float2half_rn(q2 * c + q1 * s);

    float k1 = __half2float(g_K[base + i]), k2 = __half2float(g_K[base + i + 64]);
    g_K[base + i]      = __float2half_rn(k1 * c - k2 * s);
    g_K[base + i + 64] = __float2half_rn(k2 * c + k1 * s);
}

// ---------------------------------------------------------------------------
// Fused flash attention (unchanged from R13): fp16 operands, fp32
// softmax/accum, ldmatrix fragment loads, double-buffered cp.async K/V.
// ---------------------------------------------------------------------------
#define TKV 64
#define NKVT (SEQ / TKV)     // 32
#define KSTH 68              // K/Q row stride (half2 words)
#define VSTH 36              // V/P row stride (half2 words)
// words: sK0 4352 | sK1 4352 | sV0 4608 | sV1 4608 | sP 4608 = 22528
#define FLASH_SMEM_BYTES (22528 * 4)   // 90,112

__global__ __launch_bounds__(256)
void flash_kernel()
{
    extern __shared__ uint32_t sm[];
    uint32_t* const sK0 = sm;
    uint32_t* const sK1 = sm + 4352;
    uint32_t* const sV0 = sm + 8704;
    uint32_t* const sV1 = sm + 13312;
    uint32_t* const sP  = sm + 17920;

    uint32_t sbase;
    asm("{ .reg .u64 t; cvta.to.shared.u64 t, %1; cvt.u32.u64 %0, t; }"
        : "=r"(sbase) : "l"(sm));

    const int tid  = threadIdx.x;
    const int lane = tid & 31;
    const int wid  = tid >> 5;
    const int g    = lane >> 2;
    const int tig  = lane & 3;
    const int bh   = blockIdx.y;
    const int q0   = blockIdx.x * 128;
    const float scale = 0.08838834764831845f;  // 128^-0.5

    // ldmatrix per-lane offsets
    const int lr8   = lane & 7;
    const int arow  = lr8 + ((lane & 8)  ? 8 : 0);
    const int acolw = (lane & 16) ? 4 : 0;
    const int brow  = lr8 + ((lane & 16) ? 8 : 0);
    const int bcolw = (lane & 8)  ? 4 : 0;

    const __half* Qg = g_Q + (size_t)bh * SEQ * DHEAD;
    const __half* Kg = g_K + (size_t)bh * SEQ * DHEAD;
    const __half* Vg = g_V + (size_t)bh * DHEAD * SEQ;

    // ---- stage Q tile (128 rows x 128 halves) into sm[0..8704) ----
    #pragma unroll
    for (int i = 0; i < 8; i++) {
        int e = i * 256 + tid;                 // 2048 chunks of 8 halves
        int row = e >> 4, c = e & 15;
        cp16s(sbase + (uint32_t)(row * KSTH + c * 4) * 4u,
              Qg + (size_t)(q0 + row) * DHEAD + c * 8);
    }
    CP_COMMIT();
    CP_WAIT0();
    __syncthreads();

    const int r0 = wid * 16 + g;               // first local q row (epilogue)
    uint32_t qf[8][4];
    #pragma unroll
    for (int ks = 0; ks < 8; ks++) {
        int row = wid * 16 + arow;
        ldsm_x4(qf[ks], sbase + (uint32_t)(row * KSTH + ks * 8 + acolw) * 4u);
    }
    __syncthreads();

    float oacc[16][4];
    #pragma unroll
    for (int nt = 0; nt < 16; nt++)
        #pragma unroll
        for (int i = 0; i < 4; i++) oacc[nt][i] = 0.f;
    float mrow0 = -1e30f, mrow1 = -1e30f;
    float lrow0 = 0.f, lrow1 = 0.f;

    auto load_kv = [&](uint32_t* dK, uint32_t* dV, int kv) {
        uint32_t aK = sbase + (uint32_t)(dK - sm) * 4u;
        uint32_t aV = sbase + (uint32_t)(dV - sm) * 4u;
        #pragma unroll
        for (int i = 0; i < 4; i++) {
            int e = i * 256 + tid;
            int kr = e >> 4, kc = e & 15;
            cp16s(aK + (uint32_t)(kr * KSTH + kc * 4) * 4u,
                  Kg + (size_t)(kv + kr) * DHEAD + kc * 8);
        }
        #pragma unroll
        for (int i = 0; i < 4; i++) {
            int e = i * 256 + tid;
            int vr = e >> 3, vc = e & 7;
            cp16s(aV + (uint32_t)(vr * VSTH + vc * 4) * 4u,
                  Vg + (size_t)vr * SEQ + kv + vc * 8);
        }
        CP_COMMIT();
    };

    load_kv(sK0, sV0, 0);

    const uint32_t aP = sbase + (uint32_t)(sP - sm) * 4u;

    for (int it = 0; it < NKVT; it++) {
        const int buf = it & 1;
        const uint32_t aK = sbase + (uint32_t)((buf ? sK1 : sK0) - sm) * 4u;
        const uint32_t aV = sbase + (uint32_t)((buf ? sV1 : sV0) - sm) * 4u;

        if (it + 1 < NKVT) {
            load_kv(buf ? sK0 : sK1, buf ? sV0 : sV1, (it + 1) * TKV);
            CP_WAIT1();
        } else {
            CP_WAIT0();
        }
        __syncthreads();

        // ---- S = Q K^T : 16 q rows x 64 kv cols per warp ----
        float sacc[8][4];
        #pragma unroll
        for (int nt = 0; nt < 8; nt++)
            #pragma unroll
            for (int i = 0; i < 4; i++) sacc[nt][i] = 0.f;

        #pragma unroll
        for (int ks = 0; ks < 8; ks++) {
            #pragma unroll
            for (int ntp = 0; ntp < 4; ntp++) {
                int nrow = ntp * 16 + brow;
                uint32_t bfr[4];
                ldsm_x4(bfr, aK + (uint32_t)(nrow * KSTH + ks * 8 + bcolw) * 4u);
                mma_f16(sacc[2 * ntp],     qf[ks], bfr[0], bfr[1]);
                mma_f16(sacc[2 * ntp + 1], qf[ks], bfr[2], bfr[3]);
            }
        }

        // ---- online softmax (rows r0, r0+8) ----
        float tm0 = -1e30f, tm1 = -1e30f;
        #pragma unroll
        for (int nt = 0; nt < 8; nt++) {
            tm0 = fmaxf(tm0, fmaxf(sacc[nt][0], sacc[nt][1]));
            tm1 = fmaxf(tm1, fmaxf(sacc[nt][2], sacc[nt][3]));
        }
        tm0 = fmaxf(tm0, __shfl_xor_sync(0xffffffffu, tm0, 1));
        tm0 = fmaxf(tm0, __shfl_xor_sync(0xffffffffu, tm0, 2));
        tm1 = fmaxf(tm1, __shfl_xor_sync(0xffffffffu, tm1, 1));
        tm1 = fmaxf(tm1, __shfl_xor_sync(0xffffffffu, tm1, 2));

        float mn0 = fmaxf(mrow0, tm0 * scale);
        float mn1 = fmaxf(mrow1, tm1 * scale);
        float sf0 = __expf(mrow0 - mn0);
        float sf1 = __expf(mrow1 - mn1);
        mrow0 = mn0; mrow1 = mn1;

        float rs0 = 0.f, rs1 = 0.f;
        #pragma unroll
        for (int nt = 0; nt < 8; nt++) {
            float p0 = __expf(sacc[nt][0] * scale - mn0);
            float p1 = __expf(sacc[nt][1] * scale - mn0);
            float p2 = __expf(sacc[nt][2] * scale - mn1);
            float p3 = __expf(sacc[nt][3] * scale - mn1);
            rs0 += p0 + p1;
            rs1 += p2 + p3;
            sP[r0 * VSTH + nt * 4 + tig]       = h2u(__floats2half2_rn(p0, p1));
            sP[(r0 + 8) * VSTH + nt * 4 + tig] = h2u(__floats2half2_rn(p2, p3));
        }
        rs0 += __shfl_xor_sync(0xffffffffu, rs0, 1);
        rs0 += __shfl_xor_sync(0xffffffffu, rs0, 2);
        rs1 += __shfl_xor_sync(0xffffffffu, rs1, 1);
        rs1 += __shfl_xor_sync(0xffffffffu, rs1, 2);
        lrow0 = lrow0 * sf0 + rs0;
        lrow1 = lrow1 * sf1 + rs1;

        #pragma unroll
        for (int nt = 0; nt < 16; nt++) {
            oacc[nt][0] *= sf0;
            oacc[nt][1] *= sf0;
            oacc[nt][2] *= sf1;
            oacc[nt][3] *= sf1;
        }
        __syncthreads();   // sP visible to all

        // ---- O += P V ----
        #pragma unroll
        for (int ks = 0; ks < 4; ks++) {
            uint32_t afr[4];
            int prow = wid * 16 + arow;
            ldsm_x4(afr, aP + (uint32_t)(prow * VSTH + ks * 8 + acolw) * 4u);
            #pragma unroll
            for (int ntp = 0; ntp < 8; ntp++) {
                int vrow = ntp * 16 + brow;
                uint32_t bfr[4];
                ldsm_x4(bfr, aV + (uint32_t)(vrow * VSTH + ks * 8 + bcolw) * 4u);
                mma_f16(oacc[2 * ntp],     afr, bfr[0], bfr[1]);
                mma_f16(oacc[2 * ntp + 1], afr, bfr[2], bfr[3]);
            }
        }
        __syncthreads();
    }

    // ---- epilogue: normalize, write fp16 g_O ----
    float inv0 = 1.f / lrow0;
    float inv1 = 1.f / lrow1;
    int b = bh >> 4, h = bh & 15;
    __half* Og = g_O + ((size_t)(b * SEQ + q0)) * DIM + h * DHEAD;
    #pragma unroll
    for (int nt = 0; nt < 16; nt++) {
        int col = nt * 8 + 2 * tig;
        *(__half2*)(Og + (size_t)r0 * DIM + col) =
            __floats2half2_rn(oacc[nt][0] * inv0, oacc[nt][1] * inv0);
        *(__half2*)(Og + (size_t)(r0 + 8) * DIM + col) =
            __floats2half2_rn(oacc[nt][2] * inv1, oacc[nt][3] * inv1);
    }
}

// ---------------------------------------------------------------------------
// Launch: metadata order = x, w_qkv, w_out, b_out ; output fp32 [4,2048,2048]
// No static state: attributes set unconditionally (idempotent, capture-safe).
// ---------------------------------------------------------------------------
extern "C" void kernel_launch(void* const* d_in, const int* in_sizes, int n_in,
                              void* d_out, int out_size)
{
    const float* x     = (const float*)d_in[0];
    const float* w_qkv = (const float*)d_in[1];
    const float* w_out = (const float*)d_in[2];
    const float* b_out = (const float*)d_in[3];
    float* out = (float*)d_out;

    cudaFuncSetAttribute(flash_kernel,
                         cudaFuncAttributeMaxDynamicSharedMemorySize,
                         FLASH_SMEM_BYTES);
    cudaFuncSetAttribute(gemm_nt<0>,
                         cudaFuncAttributeMaxDynamicSharedMemorySize,
                         GEMM_SMEM_BYTES);
    cudaFuncSetAttribute(gemm_nt<3>,
                         cudaFuncAttributeMaxDynamicSharedMemorySize,
                         GEMM_SMEM_BYTES);

    __half* gx; __half* gwq; __half* gwo;
    cudaGetSymbolAddress((void**)&gx,  g_X);
    cudaGetSymbolAddress((void**)&gwq, g_Wqkv);
    cudaGetSymbolAddress((void**)&gwo, g_Wout);

    // Prepass: fp16-round inputs (single rounding point per operand).
    const int n4x = (BATCH * SEQ * DIM) / 4;
    const int n4q = (3 * DIM * DIM) / 4;
    const int n4o = (DIM * DIM) / 4;
    round_half<<<(n4x + 255) / 256, 256>>>((const float4*)x,     (uint2*)gx,  n4x);
    round_half<<<(n4q + 255) / 256, 256>>>((const float4*)w_qkv, (uint2*)gwq, n4q);
    round_half<<<(n4o + 255) / 256, 256>>>((const float4*)w_out, (uint2*)gwo, n4o);

    // QKV projection: [8192,2048] x [6144,2048]^T -> Q/K/V fp16 layouts
    gemm_nt<0><<<dim3(96, 64, 1), 256, GEMM_SMEM_BYTES>>>(nullptr, nullptr, 2048);
    // RoPE in place on Q, K
    rope_kernel<<<(BHTOT * SEQ * 64) / 256, 256>>>();
    // Fused attention -> g_O (fp16)
    flash_kernel<<<dim3(16, 64, 1), 256, FLASH_SMEM_BYTES>>>();
    // Output projection + bias: [8192,2048] x [2048,2048]^T -> fp32 out
    gemm_nt<3><<<dim3(32, 64, 1), 256, GEMM_SMEM_BYTES>>>(b_out, out, 2048);
}